// round 5
// baseline (speedup 1.0000x reference)
#include <cuda_runtime.h>

#define BB 8
#define CC 64
#define NN 400
#define NN2 (NN * NN)          // 160000
#define NV4 (NN / 4)           // 100 float4 per row
#define NS 8                   // n-split chunks per batch in k2
#define NCHUNK (NN / NS)       // 50
#define KT 32                  // k-tile width in epilogue
#define PAIRS 4
#define PB 2                   // batches per pair (82 MB of R -> fits 126 MB L2)
#define CS 4                   // channel-split in k1p (for occupancy)
#define CPC (CC / CS)          // 16 channels per chunk

// Scratch (device globals; reused across pairs)
__device__ float g_pm[CS * PB * NN2];       // partial channel-max      (5.12 MB)
__device__ float g_At[BB * NN2];            // At[b][n][k] = A[b][k][n] (5.12 MB)
__device__ float g_xp[NS * BB * CC * NN];   // partial x sums           (6.55 MB)

// ---------------------------------------------------------------------------
// k1p: partial channel max over 16 channels, for one batch pair.
// Proven float4 / 4-chain streaming structure (80.6% DRAM SOL in R1),
// channel-split x4 so the 2-batch launch still has 320K threads.
//   g_pm[cs][bl][i] = max_{c in chunk cs} R[b, c, i]
// ---------------------------------------------------------------------------
__global__ void k1p_maxpart(const float* __restrict__ R, int pair) {
    const int per_b = NN2 / 4;                          // 40000 float4 per plane
    int t = blockIdx.x * blockDim.x + threadIdx.x;      // exact grid, no bound check
    int cs  = t / (PB * per_b);
    int rem = t - cs * (PB * per_b);
    int bl  = rem / per_b;
    int i4  = (rem - bl * per_b) * 4;
    int b   = pair * PB + bl;

    const float4* base = reinterpret_cast<const float4*>(
        R + (size_t)(b * CC + cs * CPC) * NN2 + i4);
    const size_t plane4 = NN2 / 4;

    float4 m0 = base[0];
    float4 m1 = base[plane4];
    float4 m2 = base[2 * plane4];
    float4 m3 = base[3 * plane4];
    #pragma unroll
    for (int c = 4; c < CPC; c += 4) {
        float4 v0 = base[(size_t)(c + 0) * plane4];
        float4 v1 = base[(size_t)(c + 1) * plane4];
        float4 v2 = base[(size_t)(c + 2) * plane4];
        float4 v3 = base[(size_t)(c + 3) * plane4];
        m0.x = fmaxf(m0.x, v0.x); m0.y = fmaxf(m0.y, v0.y); m0.z = fmaxf(m0.z, v0.z); m0.w = fmaxf(m0.w, v0.w);
        m1.x = fmaxf(m1.x, v1.x); m1.y = fmaxf(m1.y, v1.y); m1.z = fmaxf(m1.z, v1.z); m1.w = fmaxf(m1.w, v1.w);
        m2.x = fmaxf(m2.x, v2.x); m2.y = fmaxf(m2.y, v2.y); m2.z = fmaxf(m2.z, v2.z); m2.w = fmaxf(m2.w, v2.w);
        m3.x = fmaxf(m3.x, v3.x); m3.y = fmaxf(m3.y, v3.y); m3.z = fmaxf(m3.z, v3.z); m3.w = fmaxf(m3.w, v3.w);
    }
    float4 m;
    m.x = fmaxf(fmaxf(m0.x, m1.x), fmaxf(m2.x, m3.x));
    m.y = fmaxf(fmaxf(m0.y, m1.y), fmaxf(m2.y, m3.y));
    m.z = fmaxf(fmaxf(m0.z, m1.z), fmaxf(m2.z, m3.z));
    m.w = fmaxf(fmaxf(m0.w, m1.w), fmaxf(m2.w, m3.w));

    reinterpret_cast<float4*>(g_pm + (size_t)(cs * PB + bl) * NN2 + i4)[0] = m;
}

// ---------------------------------------------------------------------------
// kCp: combine CS partial maxes + relu(tanh) + 32x32 tile TRANSPOSE -> g_At.
// Reads g_pm (L2-hot), writes At[b][j][i]. Small kernel (~6.5 MB traffic).
// ---------------------------------------------------------------------------
__global__ void kCp_combineT(int pair) {
    __shared__ float t[32][33];
    const int bl = blockIdx.z;
    const int b  = pair * PB + bl;
    const int i0 = blockIdx.y * 32;                     // row of A (slow dim)
    const int j0 = blockIdx.x * 32;                     // col of A (fast dim)
    const int x  = threadIdx.x;
    const int y  = threadIdx.y;

    #pragma unroll
    for (int q = 0; q < 4; ++q) {
        int i = i0 + y + 8 * q;
        int j = j0 + x;
        if (i < NN && j < NN) {
            size_t off = (size_t)i * NN + j;
            float m = g_pm[(size_t)(0 * PB + bl) * NN2 + off];
            m = fmaxf(m, g_pm[(size_t)(1 * PB + bl) * NN2 + off]);
            m = fmaxf(m, g_pm[(size_t)(2 * PB + bl) * NN2 + off]);
            m = fmaxf(m, g_pm[(size_t)(3 * PB + bl) * NN2 + off]);
            t[y + 8 * q][x] = (m > 0.f) ? tanhf(m) : 0.f;
        }
    }
    __syncthreads();

    float* Atb = g_At + (size_t)b * NN2;
    #pragma unroll
    for (int q = 0; q < 4; ++q) {
        int j = j0 + y + 8 * q;                         // row of At
        int i = i0 + x;                                 // fast dim of At
        if (j < NN && i < NN)
            Atb[(size_t)j * NN + i] = t[x][y + 8 * q];
    }
}

// ---------------------------------------------------------------------------
// k2p: partial gather for one batch pair (R re-read should hit L2).
//   xp[s][b][c][k] = sum_{n in chunk s} R[b,c,n,k] * At[b,n,k]
// Grid (4 kt, 8 cg, PB*NS) = 512 blocks. Proven inner loop from R3/R4.
// ---------------------------------------------------------------------------
__global__ void k2p_gather(const float* __restrict__ R, int pair) {
    const int bz = blockIdx.z;
    const int bl = bz / NS;
    const int ns = bz - bl * NS;
    const int b  = pair * PB + bl;
    const int cg = blockIdx.y;
    const int kt = blockIdx.x;
    const int x  = threadIdx.x;
    const int y  = threadIdx.y;
    const int c  = cg * 8 + y;
    const int k4 = kt * 32 + x;
    if (k4 >= NV4) return;

    const int n0 = ns * NCHUNK;
    const float4* Rv = reinterpret_cast<const float4*>(
                           R + (size_t)(b * CC + c) * NN2) + (size_t)n0 * NV4 + k4;
    const float4* Av = reinterpret_cast<const float4*>(
                           g_At + (size_t)b * NN2) + (size_t)n0 * NV4 + k4;

    float4 s0 = make_float4(0.f, 0.f, 0.f, 0.f);
    float4 s1 = make_float4(0.f, 0.f, 0.f, 0.f);
    #pragma unroll 5
    for (int n = 0; n < NCHUNK; n += 2) {
        float4 a0 = Av[(size_t)n * NV4];
        float4 r0 = Rv[(size_t)n * NV4];
        float4 a1 = Av[(size_t)(n + 1) * NV4];
        float4 r1 = Rv[(size_t)(n + 1) * NV4];
        s0.x = fmaf(r0.x, a0.x, s0.x); s0.y = fmaf(r0.y, a0.y, s0.y);
        s0.z = fmaf(r0.z, a0.z, s0.z); s0.w = fmaf(r0.w, a0.w, s0.w);
        s1.x = fmaf(r1.x, a1.x, s1.x); s1.y = fmaf(r1.y, a1.y, s1.y);
        s1.z = fmaf(r1.z, a1.z, s1.z); s1.w = fmaf(r1.w, a1.w, s1.w);
    }
    float4 o;
    o.x = s0.x + s1.x; o.y = s0.y + s1.y;
    o.z = s0.z + s1.z; o.w = s0.w + s1.w;
    reinterpret_cast<float4*>(g_xp)[(((size_t)ns * BB + b) * CC + c) * NV4 + k4] = o;
}

// ---------------------------------------------------------------------------
// k3f: fused reduce + linear.
//   out[b,o,k] = sum_c W[o,c] * (sum_s xp[s][b][c][k]) + bias[o]
// Grid (13, 4 o-groups, 8 b) = 416 blocks; xp reads are L2-hot (just written).
// ---------------------------------------------------------------------------
__global__ void k3f_linear(const float* __restrict__ W,
                           const float* __restrict__ bias,
                           float* __restrict__ out) {
    __shared__ float xs[CC][KT + 1];
    const int b  = blockIdx.z;
    const int og = blockIdx.y;                // 0..3
    const int k0 = blockIdx.x * KT;
    const int x  = threadIdx.x;
    const int y  = threadIdx.y;
    const int k  = k0 + x;
    const bool valid = (k < NN);
    const int kc = valid ? k : (NN - 1);

    for (int c = y; c < CC; c += 8) {
        float s = 0.f;
        #pragma unroll
        for (int ssi = 0; ssi < NS; ++ssi)
            s += g_xp[(((size_t)ssi * BB + b) * CC + c) * NN + kc];
        xs[c][x] = s;
    }
    __syncthreads();

    #pragma unroll
    for (int oi = 0; oi < 2; ++oi) {
        int o = og * 16 + y + oi * 8;
        float acc = bias[o];
        const float* wr = W + o * CC;
        #pragma unroll 16
        for (int c = 0; c < CC; ++c)
            acc = fmaf(wr[c], xs[c][x], acc);
        if (valid)
            out[((size_t)b * CC + o) * NN + k] = acc;
    }
}

// ---------------------------------------------------------------------------
extern "C" void kernel_launch(void* const* d_in, const int* in_sizes, int n_in,
                              void* d_out, int out_size) {
    const float* R    = (const float*)d_in[0];
    const float* W    = (const float*)d_in[1];
    const float* bias = (const float*)d_in[2];
    float*       out  = (float*)d_out;

    for (int p = 0; p < PAIRS; ++p) {
        // k1p: CS*PB*40000 = 320000 threads -> 1250 blocks x 256 (exact)
        k1p_maxpart<<<1250, 256>>>(R, p);

        // kCp: combine + transpose, (13 x 13 x 2) = 338 blocks
        {
            dim3 grid((NN + 31) / 32, (NN + 31) / 32, PB);
            dim3 blk(32, 8);
            kCp_combineT<<<grid, blk>>>(p);
        }

        // k2p: (4 x 8 x 16) = 512 blocks — R still L2-resident from k1p
        {
            dim3 grid((NV4 + 31) / 32, 8, PB * NS);
            dim3 blk(32, 8);
            k2p_gather<<<grid, blk>>>(R, p);
        }
    }

    // Fused epilogue: 416 blocks
    {
        dim3 grid((NN + KT - 1) / KT, 4, BB);
        dim3 blk(32, 8);
        k3f_linear<<<grid, blk>>>(W, bias, out);
    }
}

// round 6
// speedup vs baseline: 1.0656x; 1.0656x over previous
#include <cuda_runtime.h>

#define BB 8
#define CC 64
#define NN 400
#define NN2 (NN * NN)          // 160000
#define NV4 (NN / 4)           // 100 float4 per row
#define NS 8                   // n-split chunks in kernel 2
#define NCHUNK (NN / NS)       // 50
#define KT 32                  // k-tile width in epilogue
#define CSP 2                  // channel split in k1 (occupancy)
#define CPC (CC / CSP)         // 32 channels per chunk

// Scratch (device globals: no allocation allowed in kernel_launch)
__device__ float g_pm[CSP * BB * NN2];      // partial channel-max      (10.2 MB)
__device__ float g_At[BB * NN2];            // At[b][n][k] = A[b][k][n] (5.12 MB)
__device__ float g_xp[NS * BB * CC * NN];   // partial x sums           (6.55 MB)
__device__ float g_x [BB * CC * NN];        // reduced x                (0.82 MB)

// ---------------------------------------------------------------------------
// Kernel 1: partial channel max, channel-split x2 for 640K threads.
// Same proven float4 / 4-chain streaming body as R1 (80.6% SOL), but twice
// the resident warps -> ~2x bytes in flight. One monolithic launch (R5 lesson:
// never fragment the big stream).
//   g_pm[cs][b][i] = max_{c in chunk cs} R[b,c,i]
// ---------------------------------------------------------------------------
__global__ void k1_maxpart(const float* __restrict__ R) {
    const int per_b = NN2 / 4;                          // 40000 float4 per plane
    int t = blockIdx.x * blockDim.x + threadIdx.x;      // exact grid: 2500*256
    int cs  = t / (BB * per_b);
    int rem = t - cs * (BB * per_b);
    int b   = rem / per_b;
    int i4  = (rem - b * per_b) * 4;

    const float4* base = reinterpret_cast<const float4*>(
        R + (size_t)(b * CC + cs * CPC) * NN2 + i4);
    const size_t plane4 = NN2 / 4;

    float4 m0 = base[0];
    float4 m1 = base[plane4];
    float4 m2 = base[2 * plane4];
    float4 m3 = base[3 * plane4];
    #pragma unroll 4
    for (int c = 4; c < CPC; c += 4) {
        float4 v0 = base[(size_t)(c + 0) * plane4];
        float4 v1 = base[(size_t)(c + 1) * plane4];
        float4 v2 = base[(size_t)(c + 2) * plane4];
        float4 v3 = base[(size_t)(c + 3) * plane4];
        m0.x = fmaxf(m0.x, v0.x); m0.y = fmaxf(m0.y, v0.y); m0.z = fmaxf(m0.z, v0.z); m0.w = fmaxf(m0.w, v0.w);
        m1.x = fmaxf(m1.x, v1.x); m1.y = fmaxf(m1.y, v1.y); m1.z = fmaxf(m1.z, v1.z); m1.w = fmaxf(m1.w, v1.w);
        m2.x = fmaxf(m2.x, v2.x); m2.y = fmaxf(m2.y, v2.y); m2.z = fmaxf(m2.z, v2.z); m2.w = fmaxf(m2.w, v2.w);
        m3.x = fmaxf(m3.x, v3.x); m3.y = fmaxf(m3.y, v3.y); m3.z = fmaxf(m3.z, v3.z); m3.w = fmaxf(m3.w, v3.w);
    }
    float4 m;
    m.x = fmaxf(fmaxf(m0.x, m1.x), fmaxf(m2.x, m3.x));
    m.y = fmaxf(fmaxf(m0.y, m1.y), fmaxf(m2.y, m3.y));
    m.z = fmaxf(fmaxf(m0.z, m1.z), fmaxf(m2.z, m3.z));
    m.w = fmaxf(fmaxf(m0.w, m1.w), fmaxf(m2.w, m3.w));

    reinterpret_cast<float4*>(g_pm + (size_t)(cs * BB + b) * NN2 + i4)[0] = m;
}

// ---------------------------------------------------------------------------
// Kernel T: combine 2 partial maxes + relu(tanh) + 32x32 tile transpose.
//   g_At[b][n][k] = relu(tanh(max(pm0[b][k][n], pm1[b][k][n])))
// Reads 10.2 MB (L2-hot from k1), writes 5.1 MB.
// ---------------------------------------------------------------------------
__global__ void kT_combineT() {
    __shared__ float t[32][33];
    const int b  = blockIdx.z;
    const int k0 = blockIdx.y * 32;           // slow dim of pm (row)
    const int n0 = blockIdx.x * 32;           // fast dim of pm (col)
    const int x  = threadIdx.x;
    const int y  = threadIdx.y;

    const float* p0 = g_pm + (size_t)b * NN2;
    const float* p1 = g_pm + (size_t)(BB + b) * NN2;
    #pragma unroll
    for (int q = 0; q < 4; ++q) {
        int k = k0 + y + 8 * q;
        int n = n0 + x;
        if (k < NN && n < NN) {
            size_t off = (size_t)k * NN + n;
            float m = fmaxf(p0[off], p1[off]);
            t[y + 8 * q][x] = (m > 0.f) ? tanhf(m) : 0.f;
        }
    }
    __syncthreads();

    float* Atb = g_At + (size_t)b * NN2;
    #pragma unroll
    for (int q = 0; q < 4; ++q) {
        int n = n0 + y + 8 * q;
        int k = k0 + x;
        if (n < NN && k < NN)
            Atb[(size_t)n * NN + k] = t[x][y + 8 * q];
    }
}

// ---------------------------------------------------------------------------
// Kernel 2 (R4 verbatim): partial gather, n split into NS chunks.
//   xp[s][b][c][k] = sum_{n in chunk s} R[b,c,n,k] * At[b,n,k]
// Grid (4 kt, 8 cg, BB*NS) = 2048 blocks; pure float4 streams.
// ---------------------------------------------------------------------------
__global__ void k2_gather(const float* __restrict__ R) {
    const int bz = blockIdx.z;
    const int b  = bz / NS;
    const int ns = bz - b * NS;
    const int cg = blockIdx.y;
    const int kt = blockIdx.x;
    const int x  = threadIdx.x;
    const int y  = threadIdx.y;
    const int c  = cg * 8 + y;
    const int k4 = kt * 32 + x;
    if (k4 >= NV4) return;

    const int n0 = ns * NCHUNK;
    const float4* Rv = reinterpret_cast<const float4*>(
                           R + (size_t)(b * CC + c) * NN2) + (size_t)n0 * NV4 + k4;
    const float4* Av = reinterpret_cast<const float4*>(
                           g_At + (size_t)b * NN2) + (size_t)n0 * NV4 + k4;

    float4 s0 = make_float4(0.f, 0.f, 0.f, 0.f);
    float4 s1 = make_float4(0.f, 0.f, 0.f, 0.f);
    #pragma unroll 5
    for (int n = 0; n < NCHUNK; n += 2) {
        float4 a0 = Av[(size_t)n * NV4];
        float4 r0 = Rv[(size_t)n * NV4];
        float4 a1 = Av[(size_t)(n + 1) * NV4];
        float4 r1 = Rv[(size_t)(n + 1) * NV4];
        s0.x = fmaf(r0.x, a0.x, s0.x); s0.y = fmaf(r0.y, a0.y, s0.y);
        s0.z = fmaf(r0.z, a0.z, s0.z); s0.w = fmaf(r0.w, a0.w, s0.w);
        s1.x = fmaf(r1.x, a1.x, s1.x); s1.y = fmaf(r1.y, a1.y, s1.y);
        s1.z = fmaf(r1.z, a1.z, s1.z); s1.w = fmaf(r1.w, a1.w, s1.w);
    }
    float4 o;
    o.x = s0.x + s1.x; o.y = s0.y + s1.y;
    o.z = s0.z + s1.z; o.w = s0.w + s1.w;
    reinterpret_cast<float4*>(g_xp)[(((size_t)ns * BB + b) * CC + c) * NV4 + k4] = o;
}

// ---------------------------------------------------------------------------
// Kernel 3a (R4 verbatim): g_x = sum_s g_xp[s] — flat float4 reduce.
// ---------------------------------------------------------------------------
__global__ void k3a_reduce() {
    const int total4 = BB * CC * NV4;                  // 51200
    int t = blockIdx.x * blockDim.x + threadIdx.x;
    if (t >= total4) return;
    const float4* xp4 = reinterpret_cast<const float4*>(g_xp);
    const int stride4 = BB * CC * NV4;

    float4 s = xp4[t];
    #pragma unroll
    for (int ssi = 1; ssi < NS; ++ssi) {
        float4 v = xp4[(size_t)ssi * stride4 + t];
        s.x += v.x; s.y += v.y; s.z += v.z; s.w += v.w;
    }
    reinterpret_cast<float4*>(g_x)[t] = s;
}

// ---------------------------------------------------------------------------
// Kernel 3b (R4 verbatim): out[b,o,k] = sum_c W[o,c] * x[b,c,k] + bias[o]
// ---------------------------------------------------------------------------
__global__ void k3b_linear(const float* __restrict__ W,
                           const float* __restrict__ bias,
                           float* __restrict__ out) {
    __shared__ float xs[CC][KT + 1];
    const int b  = blockIdx.z;
    const int og = blockIdx.y;
    const int k0 = blockIdx.x * KT;
    const int x  = threadIdx.x;
    const int y  = threadIdx.y;
    const int k  = k0 + x;
    const bool valid = (k < NN);
    const int kc = valid ? k : (NN - 1);

    for (int c = y; c < CC; c += 8)
        xs[c][x] = g_x[((size_t)b * CC + c) * NN + kc];
    __syncthreads();

    #pragma unroll
    for (int oi = 0; oi < 2; ++oi) {
        int o = og * 16 + y + oi * 8;
        float acc = bias[o];
        const float* wr = W + o * CC;
        #pragma unroll 16
        for (int c = 0; c < CC; ++c)
            acc = fmaf(wr[c], xs[c][x], acc);
        if (valid)
            out[((size_t)b * CC + o) * NN + k] = acc;
    }
}

// ---------------------------------------------------------------------------
extern "C" void kernel_launch(void* const* d_in, const int* in_sizes, int n_in,
                              void* d_out, int out_size) {
    const float* R    = (const float*)d_in[0];
    const float* W    = (const float*)d_in[1];
    const float* bias = (const float*)d_in[2];
    float*       out  = (float*)d_out;

    // Kernel 1: CSP*BB*40000 = 640000 threads -> 2500 blocks x 256 (exact)
    k1_maxpart<<<2500, 256>>>(R);

    // Combine partials + transpose: (13 x 13 x 8)
    {
        dim3 grid((NN + 31) / 32, (NN + 31) / 32, BB);
        dim3 blk(32, 8);
        kT_combineT<<<grid, blk>>>();
    }

    // Kernel 2: 2048 blocks
    {
        dim3 grid((NV4 + 31) / 32, 8, BB * NS);
        dim3 blk(32, 8);
        k2_gather<<<grid, blk>>>(R);
    }

    // Kernel 3a: partial reduce (200 blocks)
    {
        int total4 = BB * CC * NV4;
        k3a_reduce<<<(total4 + 255) / 256, 256>>>();
    }

    // Kernel 3b: linear (416 blocks)
    {
        dim3 grid((NN + KT - 1) / KT, 4, BB);
        dim3 blk(32, 8);
        k3b_linear<<<grid, blk>>>(W, bias, out);
    }
}